// round 3
// baseline (speedup 1.0000x reference)
#include <cuda_runtime.h>
#include <cstdint>

// Round 3: 512-thread main kernel — 16 warps = 4 row-groups x 4 col-slices.
// Halves per-warp work, doubles warps/SMSP (2->4) to cover LDS/shfl/MUFU latency.
// KV-split x3 + cp.async double buffering + register softmax retained.

#define QT 64
#define KT 128
#define D_DIM 64
#define V_SZ 32000
#define C_DIM 768
#define NSPLIT 3
#define TPS 84
#define NBLK 96
#define NTHR 512

#define SQ_ST 68
#define SK_ST 68
#define SE_ST 72

#define SK_OFF (QT*SQ_ST)
#define SE_OFF (SK_OFF + 2*KT*SK_ST)
#define SMEM_FLOATS (SE_OFF + 2*KT*SE_ST)
#define SMEM_BYTES (SMEM_FLOATS*4)

__device__ float g_Oscr[NSPLIT][NBLK][QT][D_DIM];
__device__ float g_Ms[NSPLIT][NBLK][QT];
__device__ float g_Ls[NSPLIT][NBLK][QT];

__device__ __forceinline__ float f2tf32(float x) {
    unsigned r;
    asm("cvt.rna.tf32.f32 %0, %1;" : "=r"(r) : "f"(x));
    return __uint_as_float(r);
}

__device__ __forceinline__ void mma_tf32(float* c,
    unsigned a0, unsigned a1, unsigned a2, unsigned a3,
    unsigned b0, unsigned b1)
{
    asm volatile(
        "mma.sync.aligned.m16n8k8.row.col.f32.tf32.tf32.f32 "
        "{%0,%1,%2,%3}, {%4,%5,%6,%7}, {%8,%9}, {%0,%1,%2,%3};"
        : "+f"(c[0]), "+f"(c[1]), "+f"(c[2]), "+f"(c[3])
        : "r"(a0), "r"(a1), "r"(a2), "r"(a3), "r"(b0), "r"(b1));
}

__device__ __forceinline__ void cpa16(uint32_t dst, const void* src) {
    asm volatile("cp.async.cg.shared.global [%0], [%1], 16;" :: "r"(dst), "l"(src));
}
__device__ __forceinline__ uint32_t s2u(const void* p) {
    return (uint32_t)__cvta_generic_to_shared(p);
}

extern "C" __global__ void __launch_bounds__(NTHR, 1)
vpf_main(const float* __restrict__ x,
         const float* __restrict__ Wf,
         const float* __restrict__ bfn,
         const float* __restrict__ Wv,
         const float* __restrict__ temps,
         const float* __restrict__ E)
{
    extern __shared__ float sm[];
    float* sQ = sm;                 // QT x SQ_ST
    float* sK = sm + SK_OFF;        // 2 stages x KT x SK_ST
    float* sE = sm + SE_OFF;        // 2 stages x KT x SE_ST

    const int qt  = blockIdx.x;
    const int h   = blockIdx.y;
    const int ks  = blockIdx.z;
    const int cb  = h*8 + qt;
    const int tid = threadIdx.x;
    const int warp = tid >> 5;
    const int lane = tid & 31;
    const int g  = lane >> 2;
    const int tq = lane & 3;
    const int pr = warp & 3;        // col slice: KV cols [pr*32, pr*32+32)
    const int rg = warp >> 2;       // row group: rows [rg*16, rg*16+16)
    const int rbase = rg * 16;

    const float inv_temp = 1.0f / fmaxf(temps[h], 0.1f);

    // ---- Q prologue: X -> sK(stage0), W_ffn -> sE(stage0) ----
    for (int it = tid; it < QT*16; it += NTHR) {
        int i = it >> 4, c4 = (it & 15) << 2;
        *(float4*)(sK + i*SK_ST + c4) =
            *(const float4*)(x + (size_t)(qt*QT + i)*C_DIM + h*D_DIM + c4);
    }
    for (int it = tid; it < D_DIM*16; it += NTHR) {
        int e = it >> 4, c4 = (it & 15) << 2;
        *(float4*)(sE + e*SE_ST + c4) =
            *(const float4*)(Wf + ((size_t)h*D_DIM + e)*D_DIM + c4);
    }
    __syncthreads();
    {
        int i = tid >> 3, q = tid & 7;
        for (int j = 0; j < 8; j++) {
            int e = q + (j << 3);
            float acc = bfn[h*D_DIM + e];
            #pragma unroll
            for (int d = 0; d < D_DIM; d++)
                acc = fmaf(sK[i*SK_ST + d], sE[e*SE_ST + d], acc);
            sQ[i*SQ_ST + e] = f2tf32(acc * inv_temp);
        }
    }
    __syncthreads();

    // ---- per-warp state: 16 rows x (pr's 64-wide O), online softmax stats ----
    float o[8][4];
    #pragma unroll
    for (int n = 0; n < 8; n++) { o[n][0]=0.f; o[n][1]=0.f; o[n][2]=0.f; o[n][3]=0.f; }
    float st_m[2] = {-INFINITY,-INFINITY};
    float st_l[2] = {0.f,0.f};

    const int t_begin = ks * TPS;
    const int nt = (ks == 2) ? (V_SZ/KT - 2*TPS) : TPS;
    const float* Kg = Wv + (size_t)h * V_SZ * D_DIM;

    #define ISSUE(TG, S) do {                                                  \
        const float* kp_ = Kg + (size_t)(TG)*KT*D_DIM;                         \
        const float* ep_ = E + (size_t)(TG)*KT*C_DIM + h*D_DIM;                \
        float* dK_ = sK + (S)*KT*SK_ST;                                        \
        float* dE_ = sE + (S)*KT*SE_ST;                                        \
        for (int it = tid; it < KT*16; it += NTHR) {                           \
            int vi = it >> 4, c4 = (it & 15) << 2;                             \
            cpa16(s2u(dK_ + vi*SK_ST + c4), kp_ + (size_t)vi*D_DIM + c4);      \
        }                                                                      \
        for (int it = tid; it < KT*16; it += NTHR) {                           \
            int vi = it >> 4, c4 = (it & 15) << 2;                             \
            cpa16(s2u(dE_ + vi*SE_ST + c4), ep_ + (size_t)vi*C_DIM + c4);      \
        }                                                                      \
        asm volatile("cp.async.commit_group;" ::: "memory");                   \
    } while (0)

    ISSUE(t_begin, 0);

    const int psrc = (lane & ~3) | (tq >> 1);   // fragment-permute source lane

    for (int t = 0; t < nt; t++) {
        const int s = t & 1;
        asm volatile("cp.async.wait_group 0;" ::: "memory");
        __syncthreads();
        if (t + 1 < nt) ISSUE(t_begin + t + 1, s ^ 1);

        const float* cK = sK + s*KT*SK_ST;
        const float* cE = sE + s*KT*SE_ST;

        // ---- S = Q K^T : rows [rbase,rbase+16), cols [pr*32,pr*32+32) ----
        float sacc[4][4];
        #pragma unroll
        for (int j = 0; j < 4; j++)
            { sacc[j][0]=0.f; sacc[j][1]=0.f; sacc[j][2]=0.f; sacc[j][3]=0.f; }

        #pragma unroll
        for (int ki = 0; ki < 8; ki++) {
            int k0 = ki << 3;
            unsigned a0 = __float_as_uint(sQ[(rbase+g  )*SQ_ST + k0+tq  ]);
            unsigned a1 = __float_as_uint(sQ[(rbase+g+8)*SQ_ST + k0+tq  ]);
            unsigned a2 = __float_as_uint(sQ[(rbase+g  )*SQ_ST + k0+tq+4]);
            unsigned a3 = __float_as_uint(sQ[(rbase+g+8)*SQ_ST + k0+tq+4]);
            #pragma unroll
            for (int j = 0; j < 4; j++) {
                int n0 = pr*32 + (j << 3);
                unsigned b0 = __float_as_uint(cK[(n0+g)*SK_ST + k0+tq  ]);
                unsigned b1 = __float_as_uint(cK[(n0+g)*SK_ST + k0+tq+4]);
                mma_tf32(sacc[j], a0,a1,a2,a3, b0,b1);
            }
        }

        // ---- online softmax (registers; rows g and g+8) ----
        float lm[2] = {-INFINITY,-INFINITY};
        #pragma unroll
        for (int j = 0; j < 4; j++) {
            lm[0] = fmaxf(lm[0], fmaxf(sacc[j][0], sacc[j][1]));
            lm[1] = fmaxf(lm[1], fmaxf(sacc[j][2], sacc[j][3]));
        }
        #pragma unroll
        for (int r = 0; r < 2; r++) {
            lm[r] = fmaxf(lm[r], __shfl_xor_sync(0xffffffffu, lm[r], 1));
            lm[r] = fmaxf(lm[r], __shfl_xor_sync(0xffffffffu, lm[r], 2));
        }
        float mnew[2], fac[2], lsum[2] = {0.f,0.f};
        #pragma unroll
        for (int r = 0; r < 2; r++) {
            mnew[r] = fmaxf(st_m[r], lm[r]);
            fac[r]  = __expf(st_m[r] - mnew[r]);
            st_m[r] = mnew[r];
        }
        #pragma unroll
        for (int j = 0; j < 4; j++) {
            float p0 = f2tf32(__expf(sacc[j][0] - mnew[0]));
            float p1 = f2tf32(__expf(sacc[j][1] - mnew[0]));
            float p2 = f2tf32(__expf(sacc[j][2] - mnew[1]));
            float p3 = f2tf32(__expf(sacc[j][3] - mnew[1]));
            sacc[j][0]=p0; sacc[j][1]=p1; sacc[j][2]=p2; sacc[j][3]=p3;
            lsum[0] += p0 + p1;
            lsum[1] += p2 + p3;
        }
        #pragma unroll
        for (int r = 0; r < 2; r++) {
            lsum[r] += __shfl_xor_sync(0xffffffffu, lsum[r], 1);
            lsum[r] += __shfl_xor_sync(0xffffffffu, lsum[r], 2);
            st_l[r] = st_l[r]*fac[r] + lsum[r];
        }
        #pragma unroll
        for (int n = 0; n < 8; n++) {
            o[n][0] *= fac[0]; o[n][1] *= fac[0];
            o[n][2] *= fac[1]; o[n][3] *= fac[1];
        }

        // ---- O += P @ E_slice : K = pr's 32 KV rows, N = 64 ----
        #pragma unroll
        for (int kf = 0; kf < 4; kf++) {
            // c-frag (cols 2tq,2tq+1) -> a-frag (cols tq,tq+4) via shuffles
            unsigned A0, A1, A2, A3;
            {
                float x00 = __shfl_sync(0xffffffffu, sacc[kf][0], psrc);
                float x01 = __shfl_sync(0xffffffffu, sacc[kf][1], psrc);
                float y00 = __shfl_sync(0xffffffffu, sacc[kf][0], psrc+2);
                float y01 = __shfl_sync(0xffffffffu, sacc[kf][1], psrc+2);
                A0 = __float_as_uint((tq & 1) ? x01 : x00);
                A2 = __float_as_uint((tq & 1) ? y01 : y00);
                float x10 = __shfl_sync(0xffffffffu, sacc[kf][2], psrc);
                float x11 = __shfl_sync(0xffffffffu, sacc[kf][3], psrc);
                float y10 = __shfl_sync(0xffffffffu, sacc[kf][2], psrc+2);
                float y11 = __shfl_sync(0xffffffffu, sacc[kf][3], psrc+2);
                A1 = __float_as_uint((tq & 1) ? x11 : x10);
                A3 = __float_as_uint((tq & 1) ? y11 : y10);
            }
            int krow = pr*32 + (kf << 3);
            #pragma unroll
            for (int n = 0; n < 8; n++) {
                unsigned b0 = __float_as_uint(cE[(krow+tq  )*SE_ST + (n<<3)+g]);
                unsigned b1 = __float_as_uint(cE[(krow+tq+4)*SE_ST + (n<<3)+g]);
                mma_tf32(o[n], A0,A1,A2,A3, b0,b1);
            }
        }
    }

    // ---- merge 4 col-slice partials, write split-partial to scratch ----
    __syncthreads();
    float* mO = sK;             // [4][64][68]
    float* mM = sE;             // [4][64]
    float* mL = sE + 4*64;
    float* fF = sE + 8*64;

    #pragma unroll
    for (int n = 0; n < 8; n++) {
        int r0 = rbase + g, r1 = r0 + 8, c = (n<<3) + 2*tq;
        mO[(pr*64 + r0)*68 + c    ] = o[n][0];
        mO[(pr*64 + r0)*68 + c + 1] = o[n][1];
        mO[(pr*64 + r1)*68 + c    ] = o[n][2];
        mO[(pr*64 + r1)*68 + c + 1] = o[n][3];
    }
    if (tq == 0) {
        mM[pr*64 + rbase + g    ] = st_m[0];
        mL[pr*64 + rbase + g    ] = st_l[0];
        mM[pr*64 + rbase + g + 8] = st_m[1];
        mL[pr*64 + rbase + g + 8] = st_l[1];
    }
    __syncthreads();
    if (tid < QT) {
        int row = tid;
        float M = mM[row];
        #pragma unroll
        for (int p = 1; p < 4; p++) M = fmaxf(M, mM[p*64 + row]);
        float L = 0.f;
        #pragma unroll
        for (int p = 0; p < 4; p++) {
            float f = __expf(mM[p*64 + row] - M);
            fF[p*64 + row] = f;
            L += mL[p*64 + row] * f;
        }
        g_Ms[ks][cb][row] = M;
        g_Ls[ks][cb][row] = L;
    }
    __syncthreads();
    for (int e = tid; e < QT*D_DIM; e += NTHR) {
        int row = e >> 6, d = e & 63;
        float sum = 0.f;
        #pragma unroll
        for (int p = 0; p < 4; p++)
            sum += mO[(p*64 + row)*68 + d] * fF[p*64 + row];
        g_Oscr[ks][cb][row][d] = sum;
    }
}

extern "C" __global__ void __launch_bounds__(256)
vpf_combine(float* __restrict__ out)
{
    const int cb = blockIdx.x;
    const int rs = blockIdx.y;           // 16-row slice
    const int h = cb >> 3, qt = cb & 7;
    __shared__ float f[NSPLIT][16];
    __shared__ float invL[16];
    const int tid = threadIdx.x;

    if (tid < 16) {
        int row = rs*16 + tid;
        float M = -INFINITY;
        #pragma unroll
        for (int s = 0; s < NSPLIT; s++) M = fmaxf(M, g_Ms[s][cb][row]);
        float L = 0.f;
        #pragma unroll
        for (int s = 0; s < NSPLIT; s++) {
            float e_ = __expf(g_Ms[s][cb][row] - M);
            f[s][tid] = e_;
            L += g_Ls[s][cb][row] * e_;
        }
        invL[tid] = 1.0f / L;
    }
    __syncthreads();
    for (int e = tid; e < 16*D_DIM; e += 256) {
        int r = e >> 6, d = e & 63;
        int row = rs*16 + r;
        float s0 = 0.f;
        #pragma unroll
        for (int s = 0; s < NSPLIT; s++)
            s0 += g_Oscr[s][cb][row][d] * f[s][r];
        out[((size_t)(qt*QT + row))*C_DIM + h*D_DIM + d] = s0 * invL[r];
    }
}

extern "C" void kernel_launch(void* const* d_in, const int* in_sizes, int n_in,
                              void* d_out, int out_size)
{
    (void)in_sizes; (void)n_in; (void)out_size;
    const float* x     = (const float*)d_in[0];
    const float* Wf    = (const float*)d_in[1];
    const float* bfn   = (const float*)d_in[2];
    const float* Wv    = (const float*)d_in[3];
    const float* temps = (const float*)d_in[4];
    const float* E     = (const float*)d_in[5];
    float* out = (float*)d_out;

    cudaFuncSetAttribute(vpf_main, cudaFuncAttributeMaxDynamicSharedMemorySize, SMEM_BYTES);
    dim3 grid(8, 12, NSPLIT);
    vpf_main<<<grid, NTHR, SMEM_BYTES>>>(x, Wf, bfn, Wv, temps, E);
    vpf_combine<<<dim3(NBLK, 4), 256>>>(out);
}

// round 4
// speedup vs baseline: 1.1167x; 1.1167x over previous
#include <cuda_runtime.h>
#include <cstdint>

// Round 4: round-2 warp shape (8 warps: 4 col-slices x 2 row-halves) +
//  - Q a-fragments hoisted to registers (loaded once; kills 4x-redundant Q LDS)
//  - cross-tile software pipeline: softmax(t) | S(t+1) | PV(t) with double
//    accumulators; K 2-stage, E 3-stage cp.async buffering
// KV-split x3 + register softmax + combine kernel retained.

#define QT 64
#define KT 128
#define D_DIM 64
#define V_SZ 32000
#define C_DIM 768
#define NSPLIT 3
#define TPS 84
#define NBLK 96
#define NTHR 256

#define SQ_ST 68
#define SK_ST 68
#define SE_ST 72

#define SK_OFF (QT*SQ_ST)                    // 4352
#define SE_OFF (SK_OFF + 2*KT*SK_ST)         // 21760
#define SMEM_FLOATS (SE_OFF + 3*KT*SE_ST)    // 49408
#define SMEM_BYTES (SMEM_FLOATS*4)           // 197632

__device__ float g_Oscr[NSPLIT][NBLK][QT][D_DIM];
__device__ float g_Ms[NSPLIT][NBLK][QT];
__device__ float g_Ls[NSPLIT][NBLK][QT];

__device__ __forceinline__ float f2tf32(float x) {
    unsigned r;
    asm("cvt.rna.tf32.f32 %0, %1;" : "=r"(r) : "f"(x));
    return __uint_as_float(r);
}

__device__ __forceinline__ void mma_tf32(float* c,
    unsigned a0, unsigned a1, unsigned a2, unsigned a3,
    unsigned b0, unsigned b1)
{
    asm volatile(
        "mma.sync.aligned.m16n8k8.row.col.f32.tf32.tf32.f32 "
        "{%0,%1,%2,%3}, {%4,%5,%6,%7}, {%8,%9}, {%0,%1,%2,%3};"
        : "+f"(c[0]), "+f"(c[1]), "+f"(c[2]), "+f"(c[3])
        : "r"(a0), "r"(a1), "r"(a2), "r"(a3), "r"(b0), "r"(b1));
}

__device__ __forceinline__ void cpa16(uint32_t dst, const void* src) {
    asm volatile("cp.async.cg.shared.global [%0], [%1], 16;" :: "r"(dst), "l"(src));
}
__device__ __forceinline__ uint32_t s2u(const void* p) {
    return (uint32_t)__cvta_generic_to_shared(p);
}

// ---- S = Q K^T (this warp: 32 rows x 32 cols), Q from registers ----
__device__ __forceinline__ void s_compute(float (&acc)[2][4][4],
    const unsigned (&qa)[8][2][4], const float* cK, int pr, int g, int tq)
{
    #pragma unroll
    for (int mi = 0; mi < 2; mi++)
        #pragma unroll
        for (int j = 0; j < 4; j++)
            { acc[mi][j][0]=0.f; acc[mi][j][1]=0.f; acc[mi][j][2]=0.f; acc[mi][j][3]=0.f; }
    #pragma unroll
    for (int ki = 0; ki < 8; ki++) {
        int k0 = ki << 3;
        #pragma unroll
        for (int j = 0; j < 4; j++) {
            int n0 = pr*32 + (j << 3);
            unsigned b0 = __float_as_uint(cK[(n0+g)*SK_ST + k0+tq  ]);
            unsigned b1 = __float_as_uint(cK[(n0+g)*SK_ST + k0+tq+4]);
            mma_tf32(acc[0][j], qa[ki][0][0],qa[ki][0][1],qa[ki][0][2],qa[ki][0][3], b0,b1);
            mma_tf32(acc[1][j], qa[ki][1][0],qa[ki][1][1],qa[ki][1][2],qa[ki][1][3], b0,b1);
        }
    }
}

// ---- online softmax on acc (-> P in place), update stats, rescale o ----
__device__ __forceinline__ void softmax_update(float (&acc)[2][4][4],
    float (&st_m)[4], float (&st_l)[4], float (&o)[2][8][4])
{
    float lm[4] = {-INFINITY,-INFINITY,-INFINITY,-INFINITY};
    #pragma unroll
    for (int mi = 0; mi < 2; mi++)
        #pragma unroll
        for (int j = 0; j < 4; j++) {
            lm[mi*2  ] = fmaxf(lm[mi*2  ], fmaxf(acc[mi][j][0], acc[mi][j][1]));
            lm[mi*2+1] = fmaxf(lm[mi*2+1], fmaxf(acc[mi][j][2], acc[mi][j][3]));
        }
    #pragma unroll
    for (int r = 0; r < 4; r++) {
        lm[r] = fmaxf(lm[r], __shfl_xor_sync(0xffffffffu, lm[r], 1));
        lm[r] = fmaxf(lm[r], __shfl_xor_sync(0xffffffffu, lm[r], 2));
    }
    float mnew[4], fac[4], lsum[4] = {0.f,0.f,0.f,0.f};
    #pragma unroll
    for (int r = 0; r < 4; r++) {
        mnew[r] = fmaxf(st_m[r], lm[r]);
        fac[r]  = __expf(st_m[r] - mnew[r]);
        st_m[r] = mnew[r];
    }
    #pragma unroll
    for (int mi = 0; mi < 2; mi++)
        #pragma unroll
        for (int j = 0; j < 4; j++) {
            float p0 = f2tf32(__expf(acc[mi][j][0] - mnew[mi*2  ]));
            float p1 = f2tf32(__expf(acc[mi][j][1] - mnew[mi*2  ]));
            float p2 = f2tf32(__expf(acc[mi][j][2] - mnew[mi*2+1]));
            float p3 = f2tf32(__expf(acc[mi][j][3] - mnew[mi*2+1]));
            acc[mi][j][0]=p0; acc[mi][j][1]=p1; acc[mi][j][2]=p2; acc[mi][j][3]=p3;
            lsum[mi*2  ] += p0 + p1;
            lsum[mi*2+1] += p2 + p3;
        }
    #pragma unroll
    for (int r = 0; r < 4; r++) {
        lsum[r] += __shfl_xor_sync(0xffffffffu, lsum[r], 1);
        lsum[r] += __shfl_xor_sync(0xffffffffu, lsum[r], 2);
        st_l[r] = st_l[r]*fac[r] + lsum[r];
    }
    #pragma unroll
    for (int mi = 0; mi < 2; mi++)
        #pragma unroll
        for (int n = 0; n < 8; n++) {
            o[mi][n][0] *= fac[mi*2  ]; o[mi][n][1] *= fac[mi*2  ];
            o[mi][n][2] *= fac[mi*2+1]; o[mi][n][3] *= fac[mi*2+1];
        }
}

// ---- O += P @ E_slice (fragment permute via shuffles) ----
__device__ __forceinline__ void pv_accum(float (&P)[2][4][4], float (&o)[2][8][4],
    const float* cE, int pr, int g, int tq, int psrc)
{
    #pragma unroll
    for (int kf = 0; kf < 4; kf++) {
        unsigned A[2][4];
        #pragma unroll
        for (int mi = 0; mi < 2; mi++) {
            float x00 = __shfl_sync(0xffffffffu, P[mi][kf][0], psrc);
            float x01 = __shfl_sync(0xffffffffu, P[mi][kf][1], psrc);
            float y00 = __shfl_sync(0xffffffffu, P[mi][kf][0], psrc+2);
            float y01 = __shfl_sync(0xffffffffu, P[mi][kf][1], psrc+2);
            A[mi][0] = __float_as_uint((tq & 1) ? x01 : x00);
            A[mi][2] = __float_as_uint((tq & 1) ? y01 : y00);
            float x10 = __shfl_sync(0xffffffffu, P[mi][kf][2], psrc);
            float x11 = __shfl_sync(0xffffffffu, P[mi][kf][3], psrc);
            float y10 = __shfl_sync(0xffffffffu, P[mi][kf][2], psrc+2);
            float y11 = __shfl_sync(0xffffffffu, P[mi][kf][3], psrc+2);
            A[mi][1] = __float_as_uint((tq & 1) ? x11 : x10);
            A[mi][3] = __float_as_uint((tq & 1) ? y11 : y10);
        }
        int krow = pr*32 + (kf << 3);
        #pragma unroll
        for (int n = 0; n < 8; n++) {
            unsigned b0 = __float_as_uint(cE[(krow+tq  )*SE_ST + (n<<3)+g]);
            unsigned b1 = __float_as_uint(cE[(krow+tq+4)*SE_ST + (n<<3)+g]);
            mma_tf32(o[0][n], A[0][0],A[0][1],A[0][2],A[0][3], b0,b1);
            mma_tf32(o[1][n], A[1][0],A[1][1],A[1][2],A[1][3], b0,b1);
        }
    }
}

extern "C" __global__ void __launch_bounds__(NTHR, 1)
vpf_main(const float* __restrict__ x,
         const float* __restrict__ Wf,
         const float* __restrict__ bfn,
         const float* __restrict__ Wv,
         const float* __restrict__ temps,
         const float* __restrict__ E)
{
    extern __shared__ float sm[];
    float* sQ = sm;                 // QT x SQ_ST
    float* sK = sm + SK_OFF;        // 2 stages x KT x SK_ST
    float* sE = sm + SE_OFF;        // 3 stages x KT x SE_ST

    const int qt  = blockIdx.x;
    const int h   = blockIdx.y;
    const int ks  = blockIdx.z;
    const int cb  = h*8 + qt;
    const int tid = threadIdx.x;
    const int warp = tid >> 5;
    const int lane = tid & 31;
    const int g  = lane >> 2;
    const int tq = lane & 3;
    const int pr = warp >> 1;       // KV cols [pr*32, pr*32+32)
    const int rq = warp & 1;        // rows [rq*32, rq*32+32)
    const int rbase = rq * 32;
    const int psrc = (lane & ~3) | (tq >> 1);

    const float inv_temp = 1.0f / fmaxf(temps[h], 0.1f);

    // ---- Q prologue: X -> sK(stage0), W_ffn -> sE(stage0), compute sQ ----
    for (int it = tid; it < QT*16; it += NTHR) {
        int i = it >> 4, c4 = (it & 15) << 2;
        *(float4*)(sK + i*SK_ST + c4) =
            *(const float4*)(x + (size_t)(qt*QT + i)*C_DIM + h*D_DIM + c4);
    }
    for (int it = tid; it < D_DIM*16; it += NTHR) {
        int e = it >> 4, c4 = (it & 15) << 2;
        *(float4*)(sE + e*SE_ST + c4) =
            *(const float4*)(Wf + ((size_t)h*D_DIM + e)*D_DIM + c4);
    }
    __syncthreads();
    {
        int i = tid >> 2, q = tid & 3;
        for (int j = 0; j < 16; j++) {
            int e = q + (j << 2);
            float acc = bfn[h*D_DIM + e];
            #pragma unroll
            for (int d = 0; d < D_DIM; d++)
                acc = fmaf(sK[i*SK_ST + d], sE[e*SE_ST + d], acc);
            sQ[i*SQ_ST + e] = f2tf32(acc * inv_temp);
        }
    }
    __syncthreads();   // sK/sE free

    const int t_begin = ks * TPS;
    const int nt = (ks == 2) ? (V_SZ/KT - 2*TPS) : TPS;   // 84/84/82 (even)
    const float* Kg = Wv + (size_t)h * V_SZ * D_DIM;

    #define ISSUE(TG, KS_, ES_) do {                                           \
        const float* kp_ = Kg + (size_t)(TG)*KT*D_DIM;                         \
        const float* ep_ = E + (size_t)(TG)*KT*C_DIM + h*D_DIM;                \
        float* dK_ = sK + (KS_)*KT*SK_ST;                                      \
        float* dE_ = sE + (ES_)*KT*SE_ST;                                      \
        for (int it = tid; it < KT*16; it += NTHR) {                           \
            int vi = it >> 4, c4 = (it & 15) << 2;                             \
            cpa16(s2u(dK_ + vi*SK_ST + c4), kp_ + (size_t)vi*D_DIM + c4);      \
        }                                                                      \
        for (int it = tid; it < KT*16; it += NTHR) {                           \
            int vi = it >> 4, c4 = (it & 15) << 2;                             \
            cpa16(s2u(dE_ + vi*SE_ST + c4), ep_ + (size_t)vi*C_DIM + c4);      \
        }                                                                      \
        asm volatile("cp.async.commit_group;" ::: "memory");                   \
    } while (0)

    ISSUE(t_begin,     0, 0);   // G0
    ISSUE(t_begin + 1, 1, 1);   // G1

    // ---- hoist Q fragments (reads sQ only; overlaps G0/G1 flight) ----
    unsigned qa[8][2][4];
    #pragma unroll
    for (int ki = 0; ki < 8; ki++) {
        int k0 = ki << 3;
        #pragma unroll
        for (int mi = 0; mi < 2; mi++) {
            int r = rbase + mi*16;
            qa[ki][mi][0] = __float_as_uint(sQ[(r+g  )*SQ_ST + k0+tq  ]);
            qa[ki][mi][1] = __float_as_uint(sQ[(r+g+8)*SQ_ST + k0+tq  ]);
            qa[ki][mi][2] = __float_as_uint(sQ[(r+g  )*SQ_ST + k0+tq+4]);
            qa[ki][mi][3] = __float_as_uint(sQ[(r+g+8)*SQ_ST + k0+tq+4]);
        }
    }

    float o[2][8][4];
    #pragma unroll
    for (int mi = 0; mi < 2; mi++)
        #pragma unroll
        for (int n = 0; n < 8; n++)
            { o[mi][n][0]=0.f; o[mi][n][1]=0.f; o[mi][n][2]=0.f; o[mi][n][3]=0.f; }
    float st_m[4] = {-INFINITY,-INFINITY,-INFINITY,-INFINITY};
    float st_l[4] = {0.f,0.f,0.f,0.f};

    float accA[2][4][4], accB[2][4][4];

    asm volatile("cp.async.wait_group 1;" ::: "memory");   // G0 done
    __syncthreads();
    s_compute(accA, qa, sK, pr, g, tq);                    // S(0) from K stage 0

    int e0 = 0;                                            // t % 3
    for (int t = 0; t < nt; t += 2) {
        int e1 = e0 + 1; if (e1 == 3) e1 = 0;              // (t+1)%3
        int e2 = e1 + 1; if (e2 == 3) e2 = 0;              // (t+2)%3
        int e3 = e2 + 1; if (e3 == 3) e3 = 0;              // (t+3)%3

        // ---- body T=t : CUR=accA, NXT=accB ----
        asm volatile("cp.async.wait_group 0;" ::: "memory");   // G(t+1) done
        __syncthreads();
        if (t + 2 < nt) ISSUE(t_begin + t + 2, 0, e2);
        softmax_update(accA, st_m, st_l, o);
        s_compute(accB, qa, sK + 1*KT*SK_ST, pr, g, tq);       // S(t+1), K stage 1
        pv_accum(accA, o, sE + e0*KT*SE_ST, pr, g, tq, psrc);  // E(t)

        // ---- body T=t+1 : CUR=accB, NXT=accA ----
        asm volatile("cp.async.wait_group 0;" ::: "memory");   // G(t+2) done
        __syncthreads();
        if (t + 3 < nt) ISSUE(t_begin + t + 3, 1, e3);
        softmax_update(accB, st_m, st_l, o);
        if (t + 2 < nt) s_compute(accA, qa, sK, pr, g, tq);    // S(t+2), K stage 0
        pv_accum(accB, o, sE + e1*KT*SE_ST, pr, g, tq, psrc);  // E(t+1)

        e0 = e2;
    }

    // ---- merge 4 col-slice partials, write split-partial to scratch ----
    __syncthreads();
    float* mO = sK;             // [4][64][68] = 69.6KB (fits 2-stage K region exactly)
    float* mM = sE;             // [4][64]
    float* mL = sE + 4*64;
    float* fF = sE + 8*64;

    #pragma unroll
    for (int mi = 0; mi < 2; mi++)
        #pragma unroll
        for (int n = 0; n < 8; n++) {
            int r0 = rbase + mi*16 + g, r1 = r0 + 8, c = (n<<3) + 2*tq;
            mO[(pr*64 + r0)*68 + c    ] = o[mi][n][0];
            mO[(pr*64 + r0)*68 + c + 1] = o[mi][n][1];
            mO[(pr*64 + r1)*68 + c    ] = o[mi][n][2];
            mO[(pr*64 + r1)*68 + c + 1] = o[mi][n][3];
        }
    if (tq == 0) {
        #pragma unroll
        for (int r = 0; r < 4; r++) {
            int row = rbase + (r >> 1)*16 + (r & 1)*8 + g;
            mM[pr*64 + row] = st_m[r];
            mL[pr*64 + row] = st_l[r];
        }
    }
    __syncthreads();
    if (tid < QT) {
        int row = tid;
        float M = mM[row];
        #pragma unroll
        for (int p = 1; p < 4; p++) M = fmaxf(M, mM[p*64 + row]);
        float L = 0.f;
        #pragma unroll
        for (int p = 0; p < 4; p++) {
            float f = __expf(mM[p*64 + row] - M);
            fF[p*64 + row] = f;
            L += mL[p*64 + row] * f;
        }
        g_Ms[ks][cb][row] = M;
        g_Ls[ks][cb][row] = L;
    }
    __syncthreads();
    for (int e = tid; e < QT*D_DIM; e += NTHR) {
        int row = e >> 6, d = e & 63;
        float sum = 0.f;
        #pragma unroll
        for (int p = 0; p < 4; p++)
            sum += mO[(p*64 + row)*68 + d] * fF[p*64 + row];
        g_Oscr[ks][cb][row][d] = sum;
    }
}

extern "C" __global__ void __launch_bounds__(256)
vpf_combine(float* __restrict__ out)
{
    const int cb = blockIdx.x;
    const int rs = blockIdx.y;           // 16-row slice
    const int h = cb >> 3, qt = cb & 7;
    __shared__ float f[NSPLIT][16];
    __shared__ float invL[16];
    const int tid = threadIdx.x;

    if (tid < 16) {
        int row = rs*16 + tid;
        float M = -INFINITY;
        #pragma unroll
        for (int s = 0; s < NSPLIT; s++) M = fmaxf(M, g_Ms[s][cb][row]);
        float L = 0.f;
        #pragma unroll
        for (int s = 0; s < NSPLIT; s++) {
            float e_ = __expf(g_Ms[s][cb][row] - M);
            f[s][tid] = e_;
            L += g_Ls[s][cb][row] * e_;
        }
        invL[tid] = 1.0f / L;
    }
    __syncthreads();
    for (int e = tid; e < 16*D_DIM; e += 256) {
        int r = e >> 6, d = e & 63;
        int row = rs*16 + r;
        float s0 = 0.f;
        #pragma unroll
        for (int s = 0; s < NSPLIT; s++)
            s0 += g_Oscr[s][cb][row][d] * f[s][r];
        out[((size_t)(qt*QT + row))*C_DIM + h*D_DIM + d] = s0 * invL[r];
    }
}

extern "C" void kernel_launch(void* const* d_in, const int* in_sizes, int n_in,
                              void* d_out, int out_size)
{
    (void)in_sizes; (void)n_in; (void)out_size;
    const float* x     = (const float*)d_in[0];
    const float* Wf    = (const float*)d_in[1];
    const float* bfn   = (const float*)d_in[2];
    const float* Wv    = (const float*)d_in[3];
    const float* temps = (const float*)d_in[4];
    const float* E     = (const float*)d_in[5];
    float* out = (float*)d_out;

    cudaFuncSetAttribute(vpf_main, cudaFuncAttributeMaxDynamicSharedMemorySize, SMEM_BYTES);
    dim3 grid(8, 12, NSPLIT);
    vpf_main<<<grid, NTHR, SMEM_BYTES>>>(x, Wf, bfn, Wv, temps, E);
    vpf_combine<<<dim3(NBLK, 4), 256>>>(out);
}